// round 5
// baseline (speedup 1.0000x reference)
#include <cuda_runtime.h>

// Problem constants (fixed by the reference).
#define BATCH   32
#define NIN     1024
#define NOUT    1024
#define DECAYF  0.8f          // 1 - 1/TAU, TAU = 5
#define CHUNK   32            // i-rows per block
#define NCHUNK  (NIN / CHUNK) // 32
#define NPAIR   (BATCH / 2)   // 16 b-pairs
#define TPB     256           // 256 threads * float4 = 1024 = NOUT

__global__ void zero_out_kernel(float* __restrict__ out) {
    int i = blockIdx.x * blockDim.x + threadIdx.x;
    if (i < BATCH * NOUT) out[i] = 0.0f;
}

__global__ __launch_bounds__(TPB) void synapse_kernel(
    const float* __restrict__ spikes,   // [B, NIN]
    const float* __restrict__ mem,      // [B, NOUT]
    const float* __restrict__ rev,      // [B, NIN]
    const float* __restrict__ syn,      // [B, NIN, NOUT]
    const float* __restrict__ weights,  // [NIN, NOUT]
    float* __restrict__ out)            // [B, NOUT], pre-zeroed
{
    __shared__ float s_rev[2][CHUNK];
    __shared__ float s_spk[2][CHUNK];

    const int b0 = blockIdx.y * 2;      // this block handles batches b0, b0+1
    const int b1 = b0 + 1;
    const int i0 = blockIdx.z * CHUNK;
    const int o4 = threadIdx.x * 4;     // first of this thread's 4 outputs

    // Stage the per-i broadcast operands for both batches.
    if (threadIdx.x < CHUNK) {
        s_rev[0][threadIdx.x] = rev[b0 * NIN + i0 + threadIdx.x];
        s_spk[0][threadIdx.x] = spikes[b0 * NIN + i0 + threadIdx.x];
        s_rev[1][threadIdx.x] = rev[b1 * NIN + i0 + threadIdx.x];
        s_spk[1][threadIdx.x] = spikes[b1 * NIN + i0 + threadIdx.x];
    }
    __syncthreads();

    const float4 mA = *reinterpret_cast<const float4*>(mem + b0 * NOUT + o4);
    const float4 mB = *reinterpret_cast<const float4*>(mem + b1 * NOUT + o4);

    const float4* __restrict__ synA =
        reinterpret_cast<const float4*>(syn + ((size_t)b0 * NIN + i0) * NOUT + o4);
    const float4* __restrict__ synB =
        reinterpret_cast<const float4*>(syn + ((size_t)b1 * NIN + i0) * NOUT + o4);
    const float4* __restrict__ wp =
        reinterpret_cast<const float4*>(weights + (size_t)i0 * NOUT + o4);

    float a0 = 0.f, a1 = 0.f, a2 = 0.f, a3 = 0.f;   // batch b0 accumulators
    float c0 = 0.f, c1 = 0.f, c2 = 0.f, c3 = 0.f;   // batch b1 accumulators

    #pragma unroll 4
    for (int i = 0; i < CHUNK; ++i) {
        // syn: read-once 128 MB stream — evict-first so weights stay L2-resident
        const float4 sA = __ldcs(synA + i * (NOUT / 4));
        const float4 sB = __ldcs(synB + i * (NOUT / 4));
        const float4 w  = wp[i * (NOUT / 4)];        // L2-resident (4 MB)
        const float rA  = s_rev[0][i], pA = s_spk[0][i];
        const float rB  = s_rev[1][i], pB = s_spk[1][i];

        // v = syn*decay + spike ; acc += (v*w) * (rev - mem)
        a0 = fmaf(fmaf(sA.x, DECAYF, pA) * w.x, rA - mA.x, a0);
        a1 = fmaf(fmaf(sA.y, DECAYF, pA) * w.y, rA - mA.y, a1);
        a2 = fmaf(fmaf(sA.z, DECAYF, pA) * w.z, rA - mA.z, a2);
        a3 = fmaf(fmaf(sA.w, DECAYF, pA) * w.w, rA - mA.w, a3);

        c0 = fmaf(fmaf(sB.x, DECAYF, pB) * w.x, rB - mB.x, c0);
        c1 = fmaf(fmaf(sB.y, DECAYF, pB) * w.y, rB - mB.y, c1);
        c2 = fmaf(fmaf(sB.z, DECAYF, pB) * w.z, rB - mB.z, c2);
        c3 = fmaf(fmaf(sB.w, DECAYF, pB) * w.w, rB - mB.w, c3);
    }

    float* opA = out + b0 * NOUT + o4;
    float* opB = out + b1 * NOUT + o4;
    atomicAdd(opA + 0, a0);
    atomicAdd(opA + 1, a1);
    atomicAdd(opA + 2, a2);
    atomicAdd(opA + 3, a3);
    atomicAdd(opB + 0, c0);
    atomicAdd(opB + 1, c1);
    atomicAdd(opB + 2, c2);
    atomicAdd(opB + 3, c3);
}

extern "C" void kernel_launch(void* const* d_in, const int* in_sizes, int n_in,
                              void* d_out, int out_size) {
    // metadata order == setup_inputs dict order:
    const float* spikes  = (const float*)d_in[0];  // [32, 1024]
    const float* mem     = (const float*)d_in[1];  // [32, 1024]
    const float* rev     = (const float*)d_in[2];  // [32, 1024]
    const float* syn     = (const float*)d_in[3];  // [32, 1024, 1024]
    const float* weights = (const float*)d_in[4];  // [1024, 1024]
    float* out = (float*)d_out;

    zero_out_kernel<<<(BATCH * NOUT + TPB - 1) / TPB, TPB>>>(out);

    dim3 grid(1, NPAIR, NCHUNK);   // 16 b-pairs x 32 i-chunks = 512 blocks
    synapse_kernel<<<grid, TPB>>>(spikes, mem, rev, syn, weights, out);
}

// round 7
// speedup vs baseline: 1.2243x; 1.2243x over previous
#include <cuda_runtime.h>
#include <cstdint>

// Problem constants (fixed by the reference).
#define BATCH   32
#define NIN     1024
#define NOUT    1024
#define DECAYF  0.8f          // 1 - 1/TAU, TAU = 5
#define CHUNK   32            // i-rows per block
#define NCHUNK  (NIN / CHUNK) // 32
#define TPB     256           // 256 threads * float4 = 1024 = NOUT
#define STAGES  4             // cp.async pipeline depth (rows of syn)

__global__ void zero_out_kernel(float* __restrict__ out) {
    int i = blockIdx.x * blockDim.x + threadIdx.x;
    if (i < BATCH * NOUT) out[i] = 0.0f;
}

__device__ __forceinline__ unsigned int smem_u32(const void* p) {
    return (unsigned int)__cvta_generic_to_shared(p);
}

__device__ __forceinline__ void cp_async16(unsigned int dst_smem, const void* src_gmem) {
    asm volatile("cp.async.cg.shared.global [%0], [%1], 16;\n"
                 :: "r"(dst_smem), "l"(src_gmem) : "memory");
}
__device__ __forceinline__ void cp_commit() {
    asm volatile("cp.async.commit_group;\n" ::: "memory");
}
__device__ __forceinline__ void cp_wait3() {
    asm volatile("cp.async.wait_group 3;\n" ::: "memory");
}

__global__ __launch_bounds__(TPB, 8) void synapse_kernel(
    const float* __restrict__ spikes,   // [B, NIN]
    const float* __restrict__ mem,      // [B, NOUT]
    const float* __restrict__ rev,      // [B, NIN]
    const float* __restrict__ syn,      // [B, NIN, NOUT]
    const float* __restrict__ weights,  // [NIN, NOUT]
    float* __restrict__ out)            // [B, NOUT], pre-zeroed
{
    // Each thread stages + consumes its own 16 B per row: no cross-thread
    // sharing, so no __syncthreads needed inside the pipeline loop.
    __shared__ float4 s_syn[STAGES][TPB];   // 4 * 256 * 16 B = 16 KB
    __shared__ float  s_rev[CHUNK];
    __shared__ float  s_spk[CHUNK];

    const int b  = blockIdx.y;
    const int i0 = blockIdx.z * CHUNK;
    const int t  = threadIdx.x;
    const int o4 = t * 4;                // first of this thread's 4 outputs

    if (t < CHUNK) {
        s_rev[t] = rev[b * NIN + i0 + t];
        s_spk[t] = spikes[b * NIN + i0 + t];
    }

    const float4 m4 = *reinterpret_cast<const float4*>(mem + b * NOUT + o4);

    const float4* __restrict__ synp =
        reinterpret_cast<const float4*>(syn + ((size_t)b * NIN + i0) * NOUT) + t;
    const float4* __restrict__ wp =
        reinterpret_cast<const float4*>(weights + (size_t)i0 * NOUT) + t;

    const unsigned int sbase = smem_u32(&s_syn[0][t]);   // stage stride = TPB*16 B

    // Prologue: fill the pipeline (rows 0..STAGES-1), one commit per row.
    #pragma unroll
    for (int k = 0; k < STAGES; ++k) {
        cp_async16(sbase + k * (TPB * 16), synp + k * (NOUT / 4));
        cp_commit();
    }

    __syncthreads();   // s_rev / s_spk ready (also after prologue issue)

    float a0 = 0.f, a1 = 0.f, a2 = 0.f, a3 = 0.f;

    // One commit_group EVERY iteration (empty near the tail) keeps the
    // group count aligned: at iter i, committed = i + STAGES, and
    // wait_group(STAGES-1) guarantees row i has landed.
    #pragma unroll 4
    for (int i = 0; i < CHUNK; ++i) {
        cp_wait3();
        const float4 s = s_syn[i & (STAGES - 1)][t];
        const float4 w = __ldg(wp + i * (NOUT / 4));   // L2-resident (4 MB)
        const float  r  = s_rev[i];
        const float  sp = s_spk[i];

        a0 = fmaf(fmaf(s.x, DECAYF, sp) * w.x, r - m4.x, a0);
        a1 = fmaf(fmaf(s.y, DECAYF, sp) * w.y, r - m4.y, a1);
        a2 = fmaf(fmaf(s.z, DECAYF, sp) * w.z, r - m4.z, a2);
        a3 = fmaf(fmaf(s.w, DECAYF, sp) * w.w, r - m4.w, a3);

        const int nxt = i + STAGES;
        if (nxt < CHUNK)
            cp_async16(sbase + (nxt & (STAGES - 1)) * (TPB * 16),
                       synp + nxt * (NOUT / 4));
        cp_commit();
    }

    float* op = out + b * NOUT + o4;
    atomicAdd(op + 0, a0);
    atomicAdd(op + 1, a1);
    atomicAdd(op + 2, a2);
    atomicAdd(op + 3, a3);
}

extern "C" void kernel_launch(void* const* d_in, const int* in_sizes, int n_in,
                              void* d_out, int out_size) {
    // metadata order == setup_inputs dict order:
    const float* spikes  = (const float*)d_in[0];  // [32, 1024]
    const float* mem     = (const float*)d_in[1];  // [32, 1024]
    const float* rev     = (const float*)d_in[2];  // [32, 1024]
    const float* syn     = (const float*)d_in[3];  // [32, 1024, 1024]
    const float* weights = (const float*)d_in[4];  // [1024, 1024]
    float* out = (float*)d_out;

    zero_out_kernel<<<(BATCH * NOUT + TPB - 1) / TPB, TPB>>>(out);

    dim3 grid(1, BATCH, NCHUNK);   // 32 b x 32 i-chunks = 1024 blocks
    synapse_kernel<<<grid, TPB>>>(spikes, mem, rev, syn, weights, out);
}